// round 4
// baseline (speedup 1.0000x reference)
#include <cuda_runtime.h>
#include <cstdint>

// Problem constants
#define GB 64
#define GN 196
#define GD 768
#define GH 12
#define GHD 64
#define GSIDE 14
#define GM (GB*GN)   // 12544

// Scratch (device globals: allocation-free rule)
__device__ __align__(16) float g_q[GB*GH*GN*GHD];
__device__ __align__(16) float g_k[GB*GH*GN*GHD];
__device__ __align__(16) float g_v[GB*GH*GN*GHD];
__device__ __align__(16) float g_ctx[(size_t)GM*GD];
__device__ __align__(16) float g_hs[(size_t)GM*GD];   // tf32-rounded hidden states
__device__ __align__(16) float g_w[4*GD*GD];          // tf32-rounded weights

// ============================ helpers =======================================
__device__ __forceinline__ uint32_t smem_u32(const void* p) {
    uint32_t a;
    asm("{ .reg .u64 t; cvta.to.shared.u64 t, %1; cvt.u32.u64 %0, t; }" : "=r"(a) : "l"(p));
    return a;
}
__device__ __forceinline__ void cp16(uint32_t s, const void* g) {
    asm volatile("cp.async.cg.shared.global [%0], [%1], 16;" :: "r"(s), "l"(g));
}
__device__ __forceinline__ void cp_commit() { asm volatile("cp.async.commit_group;" ::: "memory"); }
__device__ __forceinline__ void cp_wait1()  { asm volatile("cp.async.wait_group 1;"  ::: "memory"); }

__device__ __forceinline__ uint32_t tf32_rna(float f) {
    uint32_t u;
    asm("cvt.rna.tf32.f32 %0, %1;" : "=r"(u) : "f"(f));
    return u;
}
__device__ __forceinline__ float tf32_rnaf(float f) {
    return __uint_as_float(tf32_rna(f));
}

__device__ __forceinline__ void mma_tf32(float* c, const uint32_t* a, uint32_t b0, uint32_t b1) {
    asm volatile(
        "mma.sync.aligned.m16n8k8.row.col.f32.tf32.tf32.f32 "
        "{%0,%1,%2,%3}, {%4,%5,%6,%7}, {%8,%9}, {%0,%1,%2,%3};"
        : "+f"(c[0]), "+f"(c[1]), "+f"(c[2]), "+f"(c[3])
        : "r"(a[0]), "r"(a[1]), "r"(a[2]), "r"(a[3]), "r"(b0), "r"(b1));
}

// ===================== tf32 rounding pre-pass ===============================
__global__ void round_tf32(const float* __restrict__ s, float* __restrict__ d, int n4) {
    int i = blockIdx.x * blockDim.x + threadIdx.x;
    if (i < n4) {
        float4 v = ((const float4*)s)[i];
        v.x = tf32_rnaf(v.x);
        v.y = tf32_rnaf(v.y);
        v.z = tf32_rnaf(v.z);
        v.w = tf32_rnaf(v.w);
        ((float4*)d)[i] = v;
    }
}

// ===================== tf32 mma.sync GEMM ===================================
#define BM 128
#define BN 128
#define BK 32
#define AST 36
#define BST 136
#define ASZ (BM*AST)
#define BSZ (BK*BST)
#define GEMM_SMEM ((2*ASZ + 2*BSZ)*4)    // 71680 B
#define NCH (GD/BK)                       // 24

__global__ void __launch_bounds__(256, 2)
mma_gemm(const float* __restrict__ A, const float* __restrict__ B,
         const float* __restrict__ bias, float* __restrict__ C, int headmode)
{
    extern __shared__ float smf[];
    float* As = smf;               // [2][BM][AST]
    float* Bs = smf + 2*ASZ;       // [2][BK][BST]
    const uint32_t abase = smem_u32(As);
    const uint32_t bbase = smem_u32(Bs);

    const int tid = threadIdx.x;
    const int bx = blockIdx.x, by = blockIdx.y;
    const float* Ag = A + (size_t)(by*BM)*GD;
    const float* Bg = B + bx*BN;

    auto loadA = [&](int c, int buf) {
        const float* ag = Ag + c*BK;
        const uint32_t dst = abase + buf*ASZ*4;
        #pragma unroll
        for (int it = 0; it < 4; it++) {
            int idx = tid + 256*it;
            int m = idx >> 3, k4 = idx & 7;
            cp16(dst + (m*AST + k4*4)*4, ag + (size_t)m*GD + k4*4);
        }
    };
    auto loadB = [&](int c, int buf) {
        const float* bg = Bg + (size_t)(c*BK)*GD;
        const uint32_t dst = bbase + buf*BSZ*4;
        #pragma unroll
        for (int it = 0; it < 4; it++) {
            int idx = tid + 256*it;
            int k = idx >> 5, n4 = idx & 31;
            cp16(dst + (k*BST + n4*4)*4, bg + (size_t)k*GD + n4*4);
        }
    };

    loadA(0, 0); loadB(0, 0); cp_commit();
    loadA(1, 1); loadB(1, 1); cp_commit();

    const int wid = tid >> 5, lane = tid & 31;
    const int wm = wid & 3, wn = wid >> 2;
    const int lr = lane >> 2, lq = lane & 3;

    float acc[2][8][4];
    #pragma unroll
    for (int i = 0; i < 2; i++)
        #pragma unroll
        for (int j = 0; j < 8; j++)
            #pragma unroll
            for (int k = 0; k < 4; k++) acc[i][j][k] = 0.f;

    for (int c = 0; c < NCH; c++) {
        cp_wait1();
        __syncthreads();
        const int buf = c & 1;
        const float* as = As + buf*ASZ;
        const float* bs = Bs + buf*BSZ;

        #pragma unroll
        for (int s = 0; s < 4; s++) {
            const int k0 = s*8 + lq;
            uint32_t a[2][4], b[8][2];
            #pragma unroll
            for (int mt = 0; mt < 2; mt++) {
                const int r = wm*32 + mt*16 + lr;
                a[mt][0] = __float_as_uint(as[r*AST + k0]);
                a[mt][1] = __float_as_uint(as[(r+8)*AST + k0]);
                a[mt][2] = __float_as_uint(as[r*AST + k0 + 4]);
                a[mt][3] = __float_as_uint(as[(r+8)*AST + k0 + 4]);
            }
            #pragma unroll
            for (int nt = 0; nt < 8; nt++) {
                const int n = wn*64 + nt*8 + lr;
                b[nt][0] = __float_as_uint(bs[k0*BST + n]);
                b[nt][1] = __float_as_uint(bs[(k0+4)*BST + n]);
            }
            #pragma unroll
            for (int mt = 0; mt < 2; mt++)
                #pragma unroll
                for (int nt = 0; nt < 8; nt++)
                    mma_tf32(acc[mt][nt], a[mt], b[nt][0], b[nt][1]);
        }
        __syncthreads();
        if (c + 2 < NCH) { loadA(c+2, buf); loadB(c+2, buf); }
        cp_commit();
    }

    #pragma unroll
    for (int mt = 0; mt < 2; mt++) {
        #pragma unroll
        for (int h8 = 0; h8 < 2; h8++) {
            const int row = by*BM + wm*32 + mt*16 + h8*8 + lr;
            const int bb = row / GN, nn = row % GN;
            #pragma unroll
            for (int nt = 0; nt < 8; nt++) {
                const int col = bx*BN + wn*64 + nt*8 + 2*lq;
                float2 v;
                v.x = acc[mt][nt][h8*2+0] + bias[col];
                v.y = acc[mt][nt][h8*2+1] + bias[col+1];
                if (headmode) {
                    // round: these feed the attention tf32 MMAs
                    v.x = tf32_rnaf(v.x);
                    v.y = tf32_rnaf(v.y);
                    const int h = col >> 6, hd = col & 63;
                    *(float2*)(C + (((size_t)bb*GH + h)*GN + nn)*GHD + hd) = v;
                } else {
                    *(float2*)(C + (size_t)row*GD + col) = v;
                }
            }
        }
    }
}

// ===================== attention via mma.sync ===============================
// One CTA per (b,h), 256 thr / 8 warps. Each warp owns 16-row stripes
// (stripes 0..12, warp w does st = w, w+8). Per stripe:
//   stage Q[16][64] -> smem (Pbuf area), sigma via shfl, Q frags to regs,
//   S = Q K^T via 25x8 mma, in-register mask+softmax (quad shuffles),
//   P -> smem Pbuf, ctx = P V via 25x8 mma, store.
// smem: K [200][68], V [200][72], Pbuf [8][16][204]  (strides conflict-free)
#define AKST 68
#define AVST 72
#define APST 204
#define ATT_SMEM ((200*AKST + 200*AVST + 8*16*APST)*4)   // 216448 B

__global__ void __launch_bounds__(256, 1)
attn_mma(const float* __restrict__ Q, const float* __restrict__ K,
         const float* __restrict__ V, const float* __restrict__ Wsig,
         const float* __restrict__ bsigp, const float* __restrict__ tempp,
         float* __restrict__ CTX)
{
    extern __shared__ float smf[];
    float* Ks = smf;                         // [200][68]
    float* Vs = smf + 200*AKST;              // [200][72]
    float* Pb = smf + 200*AKST + 200*AVST;   // [8][16][204]

    const int bh = blockIdx.x;
    const int b = bh / GH, h = bh % GH;
    const float* Qg = Q + (size_t)bh * GN * GHD;
    const float* Kg = K + (size_t)bh * GN * GHD;
    const float* Vg = V + (size_t)bh * GN * GHD;

    const int tid = threadIdx.x, wid = tid >> 5, lane = tid & 31;
    const int lr = lane >> 2, lq = lane & 3;

    for (int idx = tid; idx < GN*GHD; idx += 256) {
        int j = idx >> 6, d = idx & 63;
        Ks[j*AKST + d] = Kg[idx];
        Vs[j*AVST + d] = Vg[idx];
    }
    for (int idx = tid; idx < 4*GHD; idx += 256) {   // zero pad rows 196..199
        int j = GN + (idx >> 6), d = idx & 63;
        Ks[j*AKST + d] = 0.f;
        Vs[j*AVST + d] = 0.f;
    }
    __syncthreads();

    const float temper = tempp[0], bsg = bsigp[0];
    const float ws_lo = Wsig[lane], ws_hi = Wsig[lane + 32];
    float* Qst = Pb + wid * 16 * APST;       // per-warp buffer (Q stage, then P)

    for (int st = wid; st < 13; st += 8) {
        const int m0 = st * 16;

        // ---- stage Q stripe ----
        #pragma unroll
        for (int it = 0; it < 32; it++) {
            int idx = lane + 32*it;          // 0..1023
            int rr = idx >> 6, d = idx & 63;
            int src = min(m0 + rr, GN - 1);
            Qst[rr*APST + d] = Qg[src*GHD + d];
        }
        __syncwarp();

        // ---- sigma -> denom for this lane's two rows ----
        float denom_lo = 1.f, denom_hi = 1.f;
        #pragma unroll
        for (int rr = 0; rr < 16; rr++) {
            float part = Qst[rr*APST + lane]*ws_lo + Qst[rr*APST + 32 + lane]*ws_hi;
            #pragma unroll
            for (int o = 16; o > 0; o >>= 1)
                part += __shfl_xor_sync(0xffffffffu, part, o);
            float x = part + bsg;
            float sp = (x > 20.f) ? x : log1pf(expf(x));
            float sg = sp + 1e-3f;
            float stt = sg * temper;
            float dnm = 2.f * stt * stt;
            if (rr == lr)     denom_lo = dnm;
            if (rr == lr + 8) denom_hi = dnm;
        }

        // ---- Q fragments ----
        uint32_t qa[8][4];
        #pragma unroll
        for (int kk = 0; kk < 8; kk++) {
            const int k0 = kk*8;
            qa[kk][0] = __float_as_uint(Qst[lr*APST + k0 + lq]);
            qa[kk][1] = __float_as_uint(Qst[(lr+8)*APST + k0 + lq]);
            qa[kk][2] = __float_as_uint(Qst[lr*APST + k0 + lq + 4]);
            qa[kk][3] = __float_as_uint(Qst[(lr+8)*APST + k0 + lq + 4]);
        }
        __syncwarp();

        // ---- S = Q K^T ----
        float sacc[25][4];
        #pragma unroll
        for (int nt = 0; nt < 25; nt++)
            #pragma unroll
            for (int c = 0; c < 4; c++) sacc[nt][c] = 0.f;
        #pragma unroll
        for (int nt = 0; nt < 25; nt++) {
            const int n0 = nt*8;
            #pragma unroll
            for (int kk = 0; kk < 8; kk++) {
                const int k0 = kk*8;
                uint32_t b0 = __float_as_uint(Ks[(n0+lr)*AKST + k0 + lq]);
                uint32_t b1 = __float_as_uint(Ks[(n0+lr)*AKST + k0 + lq + 4]);
                mma_tf32(sacc[nt], qa[kk], b0, b1);
            }
        }

        // ---- gaussian mask * score, softmax ----
        const int ilo = m0 + lr, ihi = m0 + lr + 8;
        const int iyl = (ilo*9363) >> 17, ixl = ilo - GSIDE*iyl;
        const int iyh = (ihi*9363) >> 17, ixh = ihi - GSIDE*iyh;
        const float invlo = -1.f / denom_lo, invhi = -1.f / denom_hi;
        float mxlo = -1e30f, mxhi = -1e30f;
        #pragma unroll
        for (int nt = 0; nt < 25; nt++) {
            #pragma unroll
            for (int cc = 0; cc < 2; cc++) {
                const int j = nt*8 + 2*lq + cc;
                const int jy = (j*9363) >> 17, jx = j - GSIDE*jy;
                const bool valid = (j < GN);
                float dy = (float)(iyl - jy), dx = (float)(ixl - jx);
                float d2l = dy*dy + dx*dx;
                float vlo = valid ? __expf(d2l*invlo) * (sacc[nt][cc]*0.125f) : -1e30f;
                dy = (float)(iyh - jy); dx = (float)(ixh - jx);
                float d2h = dy*dy + dx*dx;
                float vhi = valid ? __expf(d2h*invhi) * (sacc[nt][cc+2]*0.125f) : -1e30f;
                sacc[nt][cc]   = vlo;
                sacc[nt][cc+2] = vhi;
                mxlo = fmaxf(mxlo, vlo);
                mxhi = fmaxf(mxhi, vhi);
            }
        }
        mxlo = fmaxf(mxlo, __shfl_xor_sync(0xffffffffu, mxlo, 1));
        mxlo = fmaxf(mxlo, __shfl_xor_sync(0xffffffffu, mxlo, 2));
        mxhi = fmaxf(mxhi, __shfl_xor_sync(0xffffffffu, mxhi, 1));
        mxhi = fmaxf(mxhi, __shfl_xor_sync(0xffffffffu, mxhi, 2));

        float smlo = 0.f, smhi = 0.f;
        #pragma unroll
        for (int nt = 0; nt < 25; nt++) {
            #pragma unroll
            for (int cc = 0; cc < 2; cc++) {
                const int j = nt*8 + 2*lq + cc;
                const bool valid = (j < GN);
                float elo = valid ? __expf(sacc[nt][cc]   - mxlo) : 0.f;
                float ehi = valid ? __expf(sacc[nt][cc+2] - mxhi) : 0.f;
                sacc[nt][cc]   = elo;
                sacc[nt][cc+2] = ehi;
                smlo += elo;
                smhi += ehi;
            }
        }
        smlo += __shfl_xor_sync(0xffffffffu, smlo, 1);
        smlo += __shfl_xor_sync(0xffffffffu, smlo, 2);
        smhi += __shfl_xor_sync(0xffffffffu, smhi, 1);
        smhi += __shfl_xor_sync(0xffffffffu, smhi, 2);
        const float ivlo = 1.f / smlo, ivhi = 1.f / smhi;

        // ---- write P (tf32-rounded) into per-warp buffer ----
        #pragma unroll
        for (int nt = 0; nt < 25; nt++) {
            const int col = nt*8 + 2*lq;
            float2 plo, phi;
            plo.x = tf32_rnaf(sacc[nt][0] * ivlo);
            plo.y = tf32_rnaf(sacc[nt][1] * ivlo);
            phi.x = tf32_rnaf(sacc[nt][2] * ivhi);
            phi.y = tf32_rnaf(sacc[nt][3] * ivhi);
            *(float2*)&Qst[lr*APST + col]     = plo;
            *(float2*)&Qst[(lr+8)*APST + col] = phi;
        }
        __syncwarp();

        // ---- ctx = P V ----
        float cacc[8][4];
        #pragma unroll
        for (int nt = 0; nt < 8; nt++)
            #pragma unroll
            for (int c = 0; c < 4; c++) cacc[nt][c] = 0.f;
        #pragma unroll
        for (int ks = 0; ks < 25; ks++) {
            const int kb = ks*8;
            uint32_t pa[4];
            pa[0] = __float_as_uint(Qst[lr*APST + kb + lq]);
            pa[1] = __float_as_uint(Qst[(lr+8)*APST + kb + lq]);
            pa[2] = __float_as_uint(Qst[lr*APST + kb + lq + 4]);
            pa[3] = __float_as_uint(Qst[(lr+8)*APST + kb + lq + 4]);
            #pragma unroll
            for (int nt = 0; nt < 8; nt++) {
                uint32_t b0 = __float_as_uint(Vs[(kb+lq)*AVST + nt*8 + lr]);
                uint32_t b1 = __float_as_uint(Vs[(kb+lq+4)*AVST + nt*8 + lr]);
                mma_tf32(cacc[nt], pa, b0, b1);
            }
        }

        // ---- store ctx (tf32-rounded: feeds output GEMM) ----
        if (ilo < GN) {
            const size_t base = ((size_t)(b*GN + ilo))*GD + h*GHD;
            #pragma unroll
            for (int nt = 0; nt < 8; nt++) {
                float2 v;
                v.x = tf32_rnaf(cacc[nt][0]);
                v.y = tf32_rnaf(cacc[nt][1]);
                *(float2*)&CTX[base + nt*8 + 2*lq] = v;
            }
        }
        if (ihi < GN) {
            const size_t base = ((size_t)(b*GN + ihi))*GD + h*GHD;
            #pragma unroll
            for (int nt = 0; nt < 8; nt++) {
                float2 v;
                v.x = tf32_rnaf(cacc[nt][2]);
                v.y = tf32_rnaf(cacc[nt][3]);
                *(float2*)&CTX[base + nt*8 + 2*lq] = v;
            }
        }
        __syncwarp();   // Qst reused next stripe
    }
}

// ---------------- launch ----------------------------------------------------
extern "C" void kernel_launch(void* const* d_in, const int* in_sizes, int n_in,
                              void* d_out, int out_size)
{
    const float* hs   = (const float*)d_in[0];
    const float* temp = (const float*)d_in[1];
    const float* Wq   = (const float*)d_in[2];
    const float* bq   = (const float*)d_in[3];
    const float* Wk   = (const float*)d_in[4];
    const float* bk   = (const float*)d_in[5];
    const float* Wv   = (const float*)d_in[6];
    const float* bv   = (const float*)d_in[7];
    const float* Wo   = (const float*)d_in[8];
    const float* bo   = (const float*)d_in[9];
    const float* Wsig = (const float*)d_in[10];
    const float* bsig = (const float*)d_in[11];
    float* out = (float*)d_out;

    float *gq, *gk, *gv, *gctx, *ghs, *gw;
    cudaGetSymbolAddress((void**)&gq,   g_q);
    cudaGetSymbolAddress((void**)&gk,   g_k);
    cudaGetSymbolAddress((void**)&gv,   g_v);
    cudaGetSymbolAddress((void**)&gctx, g_ctx);
    cudaGetSymbolAddress((void**)&ghs,  g_hs);
    cudaGetSymbolAddress((void**)&gw,   g_w);

    cudaFuncSetAttribute(attn_mma,
                         cudaFuncAttributeMaxDynamicSharedMemorySize,
                         ATT_SMEM);
    cudaFuncSetAttribute(mma_gemm,
                         cudaFuncAttributeMaxDynamicSharedMemorySize,
                         GEMM_SMEM);

    float* rwq = gw + 0ull*GD*GD;
    float* rwk = gw + 1ull*GD*GD;
    float* rwv = gw + 2ull*GD*GD;
    float* rwo = gw + 3ull*GD*GD;

    const int nhs4 = GM*GD/4, nw4 = GD*GD/4;
    round_tf32<<<(nhs4 + 255)/256, 256>>>(hs, ghs, nhs4);
    round_tf32<<<(nw4 + 255)/256, 256>>>(Wq, rwq, nw4);
    round_tf32<<<(nw4 + 255)/256, 256>>>(Wk, rwk, nw4);
    round_tf32<<<(nw4 + 255)/256, 256>>>(Wv, rwv, nw4);
    round_tf32<<<(nw4 + 255)/256, 256>>>(Wo, rwo, nw4);

    dim3 gg(GD/BN, GM/BM);   // (6, 98)
    mma_gemm<<<gg, 256, GEMM_SMEM>>>(ghs,  rwq, bq, gq, 1);
    mma_gemm<<<gg, 256, GEMM_SMEM>>>(ghs,  rwk, bk, gk, 1);
    mma_gemm<<<gg, 256, GEMM_SMEM>>>(ghs,  rwv, bv, gv, 1);
    attn_mma<<<GB*GH, 256, ATT_SMEM>>>(gq, gk, gv, Wsig, bsig, temp, gctx);
    mma_gemm<<<gg, 256, GEMM_SMEM>>>(gctx, rwo, bo, out, 0);
}

// round 5
// speedup vs baseline: 1.4557x; 1.4557x over previous
#include <cuda_runtime.h>
#include <cuda_fp16.h>
#include <cstdint>

// Problem constants
#define GB 64
#define GN 196
#define GD 768
#define GH 12
#define GHD 64
#define GSIDE 14
#define GM (GB*GN)   // 12544

// Scratch (device globals: allocation-free rule)
__device__ __align__(16) float  g_q[GB*GH*GN*GHD];
__device__ __align__(16) float  g_k[GB*GH*GN*GHD];
__device__ __align__(16) float  g_v[GB*GH*GN*GHD];
__device__ __align__(16) __half g_hs_h[(size_t)GM*GD];   // fp16 hidden states
__device__ __align__(16) __half g_wt_h[4*GD*GD];         // fp16 transposed weights [N][K]
__device__ __align__(16) __half g_ctx_h[(size_t)GM*GD];  // fp16 ctx

// ============================ helpers =======================================
__device__ __forceinline__ uint32_t smem_u32(const void* p) {
    uint32_t a;
    asm("{ .reg .u64 t; cvta.to.shared.u64 t, %1; cvt.u32.u64 %0, t; }" : "=r"(a) : "l"(p));
    return a;
}
__device__ __forceinline__ void cp16(uint32_t s, const void* g) {
    asm volatile("cp.async.cg.shared.global [%0], [%1], 16;" :: "r"(s), "l"(g));
}
__device__ __forceinline__ void cp_commit() { asm volatile("cp.async.commit_group;" ::: "memory"); }
__device__ __forceinline__ void cp_wait1()  { asm volatile("cp.async.wait_group 1;"  ::: "memory"); }

__device__ __forceinline__ void mma_f16(float* c, const uint32_t* a, uint32_t b0, uint32_t b1) {
    asm volatile(
        "mma.sync.aligned.m16n8k16.row.col.f32.f16.f16.f32 "
        "{%0,%1,%2,%3}, {%4,%5,%6,%7}, {%8,%9}, {%0,%1,%2,%3};"
        : "+f"(c[0]), "+f"(c[1]), "+f"(c[2]), "+f"(c[3])
        : "r"(a[0]), "r"(a[1]), "r"(a[2]), "r"(a[3]), "r"(b0), "r"(b1));
}

// ===================== conversion pre-passes ================================
// float -> half (hidden states), 4 floats per thread
__global__ void conv_f2h(const float* __restrict__ s, __half* __restrict__ d, int n4) {
    int i = blockIdx.x * blockDim.x + threadIdx.x;
    if (i < n4) {
        float4 v = ((const float4*)s)[i];
        __half2 lo = __floats2half2_rn(v.x, v.y);
        __half2 hi = __floats2half2_rn(v.z, v.w);
        uint2 o;
        o.x = *(uint32_t*)&lo;
        o.y = *(uint32_t*)&hi;
        ((uint2*)d)[i] = o;
    }
}

// transpose 768x768 float -> half [N][K]
__global__ void transpose_f2h(const float* __restrict__ S, __half* __restrict__ T) {
    __shared__ float tile[32][33];
    int tx = threadIdx.x, ty = threadIdx.y;
    int x = blockIdx.x * 32 + tx;
    int y = blockIdx.y * 32 + ty;
    #pragma unroll
    for (int j = 0; j < 32; j += 8)
        tile[ty + j][tx] = S[(size_t)(y + j) * GD + x];
    __syncthreads();
    int x2 = blockIdx.y * 32 + tx;
    int y2 = blockIdx.x * 32 + ty;
    #pragma unroll
    for (int j = 0; j < 32; j += 8)
        T[(size_t)(y2 + j) * GD + x2] = __float2half(tile[tx][ty + j]);
}

// ===================== fp16 mma.sync GEMM ===================================
// C[M,768] = A[M,768] @ WT[768,768]^T (+bias). A half row-major [M][K],
// WT half [N][K] (pre-transposed weight). 128x128 tiles, K-chunk 64 halves,
// 256 thr / 8 warps (4m x 2n), warp tile 32x64, m16n8k16.
// smem stride 72 halves: conflict-free (bank = (36r + q) mod 32 distinct).
#define BM 128
#define BN 128
#define HBK 64
#define HST 72
#define HASZ (BM*HST)                     // halves
#define HBSZ (BN*HST)
#define GEMM_SMEM ((2*HASZ + 2*HBSZ)*2)   // 73728 B
#define NCH (GD/HBK)                      // 12

__global__ void __launch_bounds__(256, 2)
mma_gemm_f16(const __half* __restrict__ A, const __half* __restrict__ BT,
             const float* __restrict__ bias, float* __restrict__ C, int headmode)
{
    extern __shared__ __half smh[];
    __half* As = smh;                 // [2][BM][HST]
    __half* Bs = smh + 2*HASZ;        // [2][BN][HST]
    const uint32_t abase = smem_u32(As);
    const uint32_t bbase = smem_u32(Bs);

    const int tid = threadIdx.x;
    const int bx = blockIdx.x, by = blockIdx.y;
    const __half* Ag = A  + (size_t)(by*BM)*GD;
    const __half* Bg = BT + (size_t)(bx*BN)*GD;

    auto loadA = [&](int c, int buf) {
        const __half* ag = Ag + c*HBK;
        const uint32_t dst = abase + buf*HASZ*2;
        #pragma unroll
        for (int it = 0; it < 4; it++) {
            int idx = tid + 256*it;            // 0..1023
            int m = idx >> 3, k8 = idx & 7;    // 8 halves per cp
            cp16(dst + (m*HST + k8*8)*2, ag + (size_t)m*GD + k8*8);
        }
    };
    auto loadB = [&](int c, int buf) {
        const __half* bg = Bg + c*HBK;
        const uint32_t dst = bbase + buf*HBSZ*2;
        #pragma unroll
        for (int it = 0; it < 4; it++) {
            int idx = tid + 256*it;
            int n = idx >> 3, k8 = idx & 7;
            cp16(dst + (n*HST + k8*8)*2, bg + (size_t)n*GD + k8*8);
        }
    };

    loadA(0, 0); loadB(0, 0); cp_commit();
    loadA(1, 1); loadB(1, 1); cp_commit();

    const int wid = tid >> 5, lane = tid & 31;
    const int wm = wid & 3, wn = wid >> 2;
    const int lr = lane >> 2, lq = lane & 3;

    float acc[2][8][4];
    #pragma unroll
    for (int i = 0; i < 2; i++)
        #pragma unroll
        for (int j = 0; j < 8; j++)
            #pragma unroll
            for (int k = 0; k < 4; k++) acc[i][j][k] = 0.f;

    for (int c = 0; c < NCH; c++) {
        cp_wait1();
        __syncthreads();
        const int buf = c & 1;
        const __half* as = As + buf*HASZ;
        const __half* bs = Bs + buf*HBSZ;

        #pragma unroll
        for (int s = 0; s < 4; s++) {
            const int k0 = s*16 + 2*lq;
            uint32_t a[2][4], b[8][2];
            #pragma unroll
            for (int mt = 0; mt < 2; mt++) {
                const int r = wm*32 + mt*16 + lr;
                a[mt][0] = *(const uint32_t*)&as[r*HST + k0];
                a[mt][1] = *(const uint32_t*)&as[(r+8)*HST + k0];
                a[mt][2] = *(const uint32_t*)&as[r*HST + k0 + 8];
                a[mt][3] = *(const uint32_t*)&as[(r+8)*HST + k0 + 8];
            }
            #pragma unroll
            for (int nt = 0; nt < 8; nt++) {
                const int n = wn*64 + nt*8 + lr;
                b[nt][0] = *(const uint32_t*)&bs[n*HST + k0];
                b[nt][1] = *(const uint32_t*)&bs[n*HST + k0 + 8];
            }
            #pragma unroll
            for (int mt = 0; mt < 2; mt++)
                #pragma unroll
                for (int nt = 0; nt < 8; nt++)
                    mma_f16(acc[mt][nt], a[mt], b[nt][0], b[nt][1]);
        }
        __syncthreads();
        if (c + 2 < NCH) { loadA(c+2, buf); loadB(c+2, buf); }
        cp_commit();
    }

    #pragma unroll
    for (int mt = 0; mt < 2; mt++) {
        #pragma unroll
        for (int h8 = 0; h8 < 2; h8++) {
            const int row = by*BM + wm*32 + mt*16 + h8*8 + lr;
            const int bb = row / GN, nn = row % GN;
            #pragma unroll
            for (int nt = 0; nt < 8; nt++) {
                const int col = bx*BN + wn*64 + nt*8 + 2*lq;
                float2 v;
                v.x = acc[mt][nt][h8*2+0] + bias[col];
                v.y = acc[mt][nt][h8*2+1] + bias[col+1];
                if (headmode) {
                    const int h = col >> 6, hd = col & 63;
                    *(float2*)(C + (((size_t)bb*GH + h)*GN + nn)*GHD + hd) = v;
                } else {
                    *(float2*)(C + (size_t)row*GD + col) = v;
                }
            }
        }
    }
}

// ---------------- Attention core (round-3 scalar, known 353us) --------------
// One CTA per (b,h), 512 thr. ctx stored as fp16 (feeds final fp16 GEMM).
#define KT_STRIDE 200
#define ATT_SMEM_FLOATS (GHD*KT_STRIDE + GN*GHD + GN*GHD + 16*4*GN)
#define ATT_SMEM_BYTES  (ATT_SMEM_FLOATS*4)

__global__ void __launch_bounds__(512, 1)
attn_kernel(const float* __restrict__ Q, const float* __restrict__ K,
            const float* __restrict__ V, const float* __restrict__ Wsig,
            const float* __restrict__ bsigp, const float* __restrict__ tempp,
            __half* __restrict__ CTX)
{
    extern __shared__ float smf[];
    float* Ks = smf;                      // [64][200]
    float* Vs = Ks + GHD*KT_STRIDE;       // [196][64]
    float* Qs = Vs + GN*GHD;              // [196][64]
    float* Ps = Qs + GN*GHD;              // [16][4][196]

    const int bh = blockIdx.x;
    const int b = bh / GH, h = bh % GH;
    const float* Qg = Q + (size_t)bh * GN * GHD;
    const float* Kg = K + (size_t)bh * GN * GHD;
    const float* Vg = V + (size_t)bh * GN * GHD;

    const int tid = threadIdx.x;

    for (int idx = tid; idx < GN*GHD; idx += 512) {
        int j = idx >> 6, d = idx & 63;
        Ks[d*KT_STRIDE + j] = Kg[idx];
        Vs[idx] = Vg[idx];
        Qs[idx] = Qg[idx];
    }
    __syncthreads();

    const int wid = tid >> 5, lane = tid & 31;
    const float temperature = tempp[0];
    const float bs = bsigp[0];
    const float ws_lo = Wsig[lane];
    const float ws_hi = Wsig[32 + lane];

    for (int p = wid; p < GN/4; p += 16) {
        const int i0 = p * 4;

        float denom[4];
        #pragma unroll
        for (int r = 0; r < 4; r++) {
            int i = i0 + r;
            float part = Qs[i*64 + lane] * ws_lo + Qs[i*64 + 32 + lane] * ws_hi;
            #pragma unroll
            for (int o = 16; o > 0; o >>= 1)
                part += __shfl_xor_sync(0xffffffffu, part, o);
            float x = part + bs;
            float sp = (x > 20.f) ? x : log1pf(expf(x));
            float sig = sp + 1e-3f;
            float st = sig * temperature;
            denom[r] = 2.f * st * st;
        }

        float acc[4][7];
        #pragma unroll
        for (int r = 0; r < 4; r++)
            #pragma unroll
            for (int t = 0; t < 7; t++) acc[r][t] = 0.f;

        #pragma unroll 4
        for (int d4 = 0; d4 < 64; d4 += 4) {
            float4 qv[4];
            #pragma unroll
            for (int r = 0; r < 4; r++)
                qv[r] = *(const float4*)&Qs[(i0 + r)*64 + d4];
            const float* kr = Ks + d4*KT_STRIDE;
            #pragma unroll
            for (int dd = 0; dd < 4; dd++) {
                float q0 = dd==0 ? qv[0].x : dd==1 ? qv[0].y : dd==2 ? qv[0].z : qv[0].w;
                float q1 = dd==0 ? qv[1].x : dd==1 ? qv[1].y : dd==2 ? qv[1].z : qv[1].w;
                float q2 = dd==0 ? qv[2].x : dd==1 ? qv[2].y : dd==2 ? qv[2].z : qv[2].w;
                float q3 = dd==0 ? qv[3].x : dd==1 ? qv[3].y : dd==2 ? qv[3].z : qv[3].w;
                #pragma unroll
                for (int t = 0; t < 7; t++) {
                    float kv = kr[dd*KT_STRIDE + lane + 32*t];
                    acc[0][t] += q0*kv;
                    acc[1][t] += q1*kv;
                    acc[2][t] += q2*kv;
                    acc[3][t] += q3*kv;
                }
            }
        }

        #pragma unroll
        for (int r = 0; r < 4; r++) {
            const int i = i0 + r;
            const int iy = i / GSIDE, ix = i % GSIDE;
            const float inv_denom = -1.f / denom[r];
            float mx = -1e30f;
            #pragma unroll
            for (int t = 0; t < 7; t++) {
                int j = lane + 32*t;
                if (j < GN) {
                    int jy = j / GSIDE, jx = j % GSIDE;
                    float dy = (float)(iy - jy), dx = (float)(ix - jx);
                    float d2 = dy*dy + dx*dx;
                    float val = __expf(d2 * inv_denom) * (acc[r][t] * 0.125f);
                    acc[r][t] = val;
                    mx = fmaxf(mx, val);
                } else {
                    acc[r][t] = -1e30f;
                }
            }
            #pragma unroll
            for (int o = 16; o > 0; o >>= 1)
                mx = fmaxf(mx, __shfl_xor_sync(0xffffffffu, mx, o));
            float sum = 0.f;
            #pragma unroll
            for (int t = 0; t < 7; t++) {
                int j = lane + 32*t;
                if (j < GN) {
                    float e = __expf(acc[r][t] - mx);
                    acc[r][t] = e;
                    sum += e;
                }
            }
            #pragma unroll
            for (int o = 16; o > 0; o >>= 1)
                sum += __shfl_xor_sync(0xffffffffu, sum, o);
            float inv = 1.f / sum;
            float* prow = Ps + (size_t)(wid*4 + r)*GN;
            #pragma unroll
            for (int t = 0; t < 7; t++) {
                int j = lane + 32*t;
                if (j < GN) prow[j] = acc[r][t] * inv;
            }
        }
        __syncwarp();

        float cA0=0.f,cB0=0.f,cA1=0.f,cB1=0.f,cA2=0.f,cB2=0.f,cA3=0.f,cB3=0.f;
        const float* p0 = Ps + (size_t)(wid*4 + 0)*GN;
        const float* p1 = Ps + (size_t)(wid*4 + 1)*GN;
        const float* p2 = Ps + (size_t)(wid*4 + 2)*GN;
        const float* p3 = Ps + (size_t)(wid*4 + 3)*GN;
        for (int j = 0; j < GN; j += 4) {
            float4 pp0 = *(const float4*)(p0 + j);
            float4 pp1 = *(const float4*)(p1 + j);
            float4 pp2 = *(const float4*)(p2 + j);
            float4 pp3 = *(const float4*)(p3 + j);
            #pragma unroll
            for (int jj = 0; jj < 4; jj++) {
                float v0 = Vs[(j + jj)*64 + lane];
                float v1 = Vs[(j + jj)*64 + lane + 32];
                float w0 = jj==0 ? pp0.x : jj==1 ? pp0.y : jj==2 ? pp0.z : pp0.w;
                float w1 = jj==0 ? pp1.x : jj==1 ? pp1.y : jj==2 ? pp1.z : pp1.w;
                float w2 = jj==0 ? pp2.x : jj==1 ? pp2.y : jj==2 ? pp2.z : pp2.w;
                float w3 = jj==0 ? pp3.x : jj==1 ? pp3.y : jj==2 ? pp3.z : pp3.w;
                cA0 += w0*v0; cB0 += w0*v1;
                cA1 += w1*v0; cB1 += w1*v1;
                cA2 += w2*v0; cB2 += w2*v1;
                cA3 += w3*v0; cB3 += w3*v1;
            }
        }

        // store ctx fp16 (feeds the fp16 output GEMM)
        {
            size_t base = ((size_t)(b*GN + i0))*GD + h*GHD;
            CTX[base + lane]             = __float2half(cA0);
            CTX[base + lane + 32]        = __float2half(cB0);
            CTX[base + GD + lane]        = __float2half(cA1);
            CTX[base + GD + lane + 32]   = __float2half(cB1);
            CTX[base + 2*GD + lane]      = __float2half(cA2);
            CTX[base + 2*GD + lane + 32] = __float2half(cB2);
            CTX[base + 3*GD + lane]      = __float2half(cA3);
            CTX[base + 3*GD + lane + 32] = __float2half(cB3);
        }
    }
}

// ---------------- launch ----------------------------------------------------
extern "C" void kernel_launch(void* const* d_in, const int* in_sizes, int n_in,
                              void* d_out, int out_size)
{
    const float* hs   = (const float*)d_in[0];
    const float* temp = (const float*)d_in[1];
    const float* Wq   = (const float*)d_in[2];
    const float* bq   = (const float*)d_in[3];
    const float* Wk   = (const float*)d_in[4];
    const float* bk   = (const float*)d_in[5];
    const float* Wv   = (const float*)d_in[6];
    const float* bv   = (const float*)d_in[7];
    const float* Wo   = (const float*)d_in[8];
    const float* bo   = (const float*)d_in[9];
    const float* Wsig = (const float*)d_in[10];
    const float* bsig = (const float*)d_in[11];
    float* out = (float*)d_out;

    float *gq, *gk, *gv;
    __half *ghs, *gwt, *gctx;
    cudaGetSymbolAddress((void**)&gq,   g_q);
    cudaGetSymbolAddress((void**)&gk,   g_k);
    cudaGetSymbolAddress((void**)&gv,   g_v);
    cudaGetSymbolAddress((void**)&ghs,  g_hs_h);
    cudaGetSymbolAddress((void**)&gwt,  g_wt_h);
    cudaGetSymbolAddress((void**)&gctx, g_ctx_h);

    cudaFuncSetAttribute(attn_kernel,
                         cudaFuncAttributeMaxDynamicSharedMemorySize,
                         ATT_SMEM_BYTES);
    cudaFuncSetAttribute(mma_gemm_f16,
                         cudaFuncAttributeMaxDynamicSharedMemorySize,
                         GEMM_SMEM);

    __half* wtq = gwt + 0ull*GD*GD;
    __half* wtk = gwt + 1ull*GD*GD;
    __half* wtv = gwt + 2ull*GD*GD;
    __half* wto = gwt + 3ull*GD*GD;

    const int nhs4 = GM*GD/4;
    conv_f2h<<<(nhs4 + 255)/256, 256>>>(hs, ghs, nhs4);
    dim3 tb(32, 8), tg(GD/32, GD/32);
    transpose_f2h<<<tg, tb>>>(Wq, wtq);
    transpose_f2h<<<tg, tb>>>(Wk, wtk);
    transpose_f2h<<<tg, tb>>>(Wv, wtv);
    transpose_f2h<<<tg, tb>>>(Wo, wto);

    dim3 gg(GD/BN, GM/BM);   // (6, 98)
    mma_gemm_f16<<<gg, 256, GEMM_SMEM>>>(ghs,  wtq, bq, gq, 1);
    mma_gemm_f16<<<gg, 256, GEMM_SMEM>>>(ghs,  wtk, bk, gk, 1);
    mma_gemm_f16<<<gg, 256, GEMM_SMEM>>>(ghs,  wtv, bv, gv, 1);
    attn_kernel<<<GB*GH, 512, ATT_SMEM_BYTES>>>(gq, gk, gv, Wsig, bsig, temp, gctx);
    mma_gemm_f16<<<gg, 256, GEMM_SMEM>>>(gctx, wto, bo, out, 0);
}